// round 1
// baseline (speedup 1.0000x reference)
#include <cuda_runtime.h>
#include <math.h>

// Problem constants
#define Bn 8
#define Sn 1024
#define En 768
#define Hn 12
#define F3 (3 * En)          // 2304
#define NQKV (Hn * F3)       // 27648
#define HE (Hn * En)         // 9216

// Scratch (allocation-free: __device__ globals)
__device__ float g_qkv[(size_t)Bn * Hn * Sn * F3];     // [B,H,S,3E]  906 MB
__device__ float g_scores[(size_t)Bn * Hn * Sn * Sn];  // [B*H,S,S]   402 MB
__device__ float g_concat[(size_t)Bn * Sn * Hn * En];  // [B,S,H,E]   302 MB

struct GemmParams {
    const float* A;   // [.., K] K-major, row stride lda
    const float* B;   // TRANS_B: [N,K] K-major (ldb); else [K,N] N-major (ldb)
    float* C;
    int K;
    int lda, ldb, ldc;
    long long strideAz, strideBz;       // per-z batch strides (elements)
    long long strideCb, strideCh;       // C offset = (z/divH)*strideCb + (z%divH)*strideCh
    int divH;
    const float* bias;                  // indexed by global n; may be null
    float alpha;
};

// EPI: 0 = plain C[coff + m*ldc + n], 1 = QKV scatter to [B,H,S,3E]
template <bool TRANS_B, int EPI>
__global__ void __launch_bounds__(256) gemm_kernel(GemmParams p)
{
    const int bn = blockIdx.x;   // N tile
    const int bm = blockIdx.y;   // M tile
    const int z  = blockIdx.z;

    __shared__ float As[8][128];
    __shared__ float Bs[8][128];

    const int tid = threadIdx.x;
    const int tx = tid & 15;     // 0..15 -> N
    const int ty = tid >> 4;     // 0..15 -> M

    const float* A = p.A + (size_t)z * p.strideAz + (size_t)bm * 128 * p.lda;
    const float* Bp = p.B + (size_t)z * p.strideBz;

    // A-tile load mapping: 128 rows x 8 cols, one float4 per thread
    const int arow = tid >> 1;            // 0..127
    const int acol = (tid & 1) * 4;       // 0 or 4
    // B-tile (NN) mapping: 8 rows x 128 cols
    const int brow = tid >> 5;            // 0..7
    const int bcol = (tid & 31) * 4;      // 0..124

    float acc[8][8];
    #pragma unroll
    for (int i = 0; i < 8; i++)
        #pragma unroll
        for (int j = 0; j < 8; j++) acc[i][j] = 0.f;

    for (int k0 = 0; k0 < p.K; k0 += 8) {
        // Load A tile (transposed into smem)
        float4 av = *(const float4*)(A + (size_t)arow * p.lda + k0 + acol);
        As[acol + 0][arow] = av.x;
        As[acol + 1][arow] = av.y;
        As[acol + 2][arow] = av.z;
        As[acol + 3][arow] = av.w;

        if (TRANS_B) {
            float4 bv = *(const float4*)(Bp + (size_t)(bn * 128 + arow) * p.ldb + k0 + acol);
            Bs[acol + 0][arow] = bv.x;
            Bs[acol + 1][arow] = bv.y;
            Bs[acol + 2][arow] = bv.z;
            Bs[acol + 3][arow] = bv.w;
        } else {
            float4 bv = *(const float4*)(Bp + (size_t)(k0 + brow) * p.ldb + bn * 128 + bcol);
            *(float4*)&Bs[brow][bcol] = bv;
        }
        __syncthreads();

        #pragma unroll
        for (int kk = 0; kk < 8; kk++) {
            float ar[8], br[8];
            float4 a0 = *(const float4*)&As[kk][ty * 8];
            float4 a1 = *(const float4*)&As[kk][ty * 8 + 4];
            ar[0]=a0.x; ar[1]=a0.y; ar[2]=a0.z; ar[3]=a0.w;
            ar[4]=a1.x; ar[5]=a1.y; ar[6]=a1.z; ar[7]=a1.w;
            float4 b0 = *(const float4*)&Bs[kk][tx * 8];
            float4 b1 = *(const float4*)&Bs[kk][tx * 8 + 4];
            br[0]=b0.x; br[1]=b0.y; br[2]=b0.z; br[3]=b0.w;
            br[4]=b1.x; br[5]=b1.y; br[6]=b1.z; br[7]=b1.w;
            #pragma unroll
            for (int i = 0; i < 8; i++)
                #pragma unroll
                for (int j = 0; j < 8; j++)
                    acc[i][j] += ar[i] * br[j];
        }
        __syncthreads();
    }

    const size_t coff = (size_t)(z / p.divH) * p.strideCb +
                        (size_t)(z % p.divH) * p.strideCh;

    #pragma unroll
    for (int i = 0; i < 8; i++) {
        const int m = bm * 128 + ty * 8 + i;
        #pragma unroll
        for (int j = 0; j < 8; j++) {
            const int n = bn * 128 + tx * 8 + j;
            float v = acc[i][j] * p.alpha;
            if (p.bias) v += __ldg(&p.bias[n]);
            if (EPI == 1) {
                // m = b*S+s ; n = h*3E+f  ->  [B,H,S,3E]
                const int b = m >> 10;
                const int s = m & 1023;
                const int h = n / F3;
                const int f = n - h * F3;
                g_qkv[(((size_t)(b * Hn + h)) * Sn + s) * F3 + f] = v;
            } else {
                p.C[coff + (size_t)m * p.ldc + n] = v;
            }
        }
    }
}

// Softmax over rows of g_scores: one block (256 thr) per 1024-element row.
__global__ void __launch_bounds__(256) softmax_kernel(float* sc)
{
    float* row = sc + (size_t)blockIdx.x * Sn;
    const int tid = threadIdx.x;
    const int lane = tid & 31;
    const int wid = tid >> 5;
    __shared__ float red[8];

    float4 v = ((const float4*)row)[tid];
    float m = fmaxf(fmaxf(v.x, v.y), fmaxf(v.z, v.w));
    #pragma unroll
    for (int o = 16; o; o >>= 1) m = fmaxf(m, __shfl_xor_sync(~0u, m, o));
    if (lane == 0) red[wid] = m;
    __syncthreads();
    float bm = red[0];
    #pragma unroll
    for (int i = 1; i < 8; i++) bm = fmaxf(bm, red[i]);
    __syncthreads();

    float4 e;
    e.x = __expf(v.x - bm);
    e.y = __expf(v.y - bm);
    e.z = __expf(v.z - bm);
    e.w = __expf(v.w - bm);
    float s = e.x + e.y + e.z + e.w;
    #pragma unroll
    for (int o = 16; o; o >>= 1) s += __shfl_xor_sync(~0u, s, o);
    if (lane == 0) red[wid] = s;
    __syncthreads();
    float bs = red[0];
    #pragma unroll
    for (int i = 1; i < 8; i++) bs += red[i];
    const float r = __frcp_rn(bs);

    e.x *= r; e.y *= r; e.z *= r; e.w *= r;
    ((float4*)row)[tid] = e;
}

extern "C" void kernel_launch(void* const* d_in, const int* in_sizes, int n_in,
                              void* d_out, int out_size)
{
    const float* x     = (const float*)d_in[0];  // [B,S,E]
    const float* qkv_w = (const float*)d_in[1];  // [H,3E,E]
    const float* qkv_b = (const float*)d_in[2];  // [H,3E]
    const float* out_w = (const float*)d_in[3];  // [E,H*E]
    const float* out_b = (const float*)d_in[4];  // [E]
    float* out = (float*)d_out;                  // [B,S,E]

    float *qkv, *scores, *concat;
    cudaGetSymbolAddress((void**)&qkv,    g_qkv);
    cudaGetSymbolAddress((void**)&scores, g_scores);
    cudaGetSymbolAddress((void**)&concat, g_concat);

    // 1) QKV projection: [8192,768] x [27648,768]^T -> scatter to [B,H,S,3E], +bias
    {
        GemmParams p = {};
        p.A = x; p.B = qkv_w; p.C = qkv;
        p.K = En; p.lda = En; p.ldb = En; p.ldc = 0;
        p.strideAz = 0; p.strideBz = 0;
        p.strideCb = 0; p.strideCh = 0; p.divH = 1;
        p.bias = qkv_b; p.alpha = 1.0f;
        gemm_kernel<true, 1><<<dim3(NQKV / 128, (Bn * Sn) / 128, 1), 256>>>(p);
    }

    // 2) Scores: per (b,h): Q[1024,768] x K[1024,768]^T * scale -> [96,1024,1024]
    {
        GemmParams p = {};
        p.A = qkv;            // Q at offset 0 within 3E row
        p.B = qkv + En;       // K at offset 768
        p.C = scores;
        p.K = En; p.lda = F3; p.ldb = F3; p.ldc = Sn;
        p.strideAz = (long long)Sn * F3;
        p.strideBz = (long long)Sn * F3;
        p.strideCb = (long long)Sn * Sn; p.strideCh = 0; p.divH = 1;
        p.bias = nullptr; p.alpha = 0.036084391824351615f; // 1/sqrt(768)
        gemm_kernel<true, 0><<<dim3(Sn / 128, Sn / 128, Bn * Hn), 256>>>(p);
    }

    // 3) Softmax rows
    softmax_kernel<<<Bn * Hn * Sn, 256>>>(scores);

    // 4) AV: per (b,h): P[1024,1024] x V[1024,768] -> concat [B,S,H,E]
    {
        GemmParams p = {};
        p.A = scores;
        p.B = qkv + 2 * En;   // V at offset 1536
        p.C = concat;
        p.K = Sn; p.lda = Sn; p.ldb = F3; p.ldc = HE;
        p.strideAz = (long long)Sn * Sn;
        p.strideBz = (long long)Sn * F3;
        p.strideCb = (long long)Sn * Hn * En;  // per-b
        p.strideCh = En;                       // per-h
        p.divH = Hn;
        p.bias = nullptr; p.alpha = 1.0f;
        gemm_kernel<false, 0><<<dim3(En / 128, Sn / 128, Bn * Hn), 256>>>(p);
    }

    // 5) Output projection: [8192,9216] x [768,9216]^T + bias -> [8192,768]
    {
        GemmParams p = {};
        p.A = concat; p.B = out_w; p.C = out;
        p.K = HE; p.lda = HE; p.ldb = HE; p.ldc = En;
        p.strideAz = 0; p.strideBz = 0;
        p.strideCb = 0; p.strideCh = 0; p.divH = 1;
        p.bias = out_b; p.alpha = 1.0f;
        gemm_kernel<true, 0><<<dim3(En / 128, (Bn * Sn) / 128, 1), 256>>>(p);
    }
}

// round 2
// speedup vs baseline: 2.2859x; 2.2859x over previous
#include <cuda_runtime.h>
#include <math.h>
#include <stdint.h>

// Problem constants
#define Bn 8
#define Sn 1024
#define En 768
#define Hn 12
#define F3 (3 * En)          // 2304
#define NQKV (Hn * F3)       // 27648
#define HE (Hn * En)         // 9216

// Scratch (allocation-free: __device__ globals)
__device__ float g_qkv[(size_t)Bn * Hn * Sn * F3];     // [B,H,S,3E]
__device__ float g_scores[(size_t)Bn * Hn * Sn * Sn];  // [B*H,S,S]
__device__ float g_concat[(size_t)Bn * Sn * Hn * En];  // [B,S,H,E]

struct GemmParams {
    const float* A;   // [.., K] K-major, row stride lda
    const float* B;   // TRANS_B: [N,K] K-major (ldb); else [K,N] N-major (ldb)
    float* C;
    int K;
    int lda, ldb, ldc;
    long long strideAz, strideBz;
    long long strideCb, strideCh;
    int divH;
    const float* bias;
    float alpha;
};

__device__ __forceinline__ uint32_t f2tf32(float x) {
    uint32_t r;
    asm("cvt.rna.tf32.f32 %0, %1;" : "=r"(r) : "f"(x));
    return r;
}

__device__ __forceinline__ void mma_tf32(float* d, const uint32_t* a, const uint32_t* b) {
    asm volatile(
        "mma.sync.aligned.m16n8k8.row.col.f32.tf32.tf32.f32 "
        "{%0,%1,%2,%3}, {%4,%5,%6,%7}, {%8,%9}, {%0,%1,%2,%3};"
        : "+f"(d[0]), "+f"(d[1]), "+f"(d[2]), "+f"(d[3])
        : "r"(a[0]), "r"(a[1]), "r"(a[2]), "r"(a[3]), "r"(b[0]), "r"(b[1]));
}

// Tensor-core tf32 GEMM. Tile 128x128x32. 8 warps (2 M x 4 N), warp tile 64x32.
// SMEM tiles are stored pre-permuted into m16n8k8 fragment order (tf32 bits).
// EPI: 0 = plain C write, 1 = QKV scatter to [B,H,S,3E]
template <bool TRANS_B, int EPI>
__global__ void __launch_bounds__(256, 2) gemm_tc(GemmParams p)
{
    // A frags: [4 ksteps][8 mtiles][32 lanes][4 regs]
    __shared__ uint32_t As[4 * 8 * 32 * 4];   // 16 KB
    // B frags: [4 ksteps][16 ntiles][32 lanes][2 regs]
    __shared__ uint32_t Bs[4 * 16 * 32 * 2];  // 16 KB

    const int tid = threadIdx.x;
    const int lane = tid & 31;
    const int wid = tid >> 5;
    const int warp_m = wid & 1;   // 0..1
    const int warp_n = wid >> 1;  // 0..3

    const int bn = blockIdx.x;
    const int bm = blockIdx.y;
    const int z  = blockIdx.z;

    const float* A = p.A + (size_t)z * p.strideAz + (size_t)bm * 128 * p.lda;
    const float* Bp = p.B + (size_t)z * p.strideBz;
    if (TRANS_B) Bp += (size_t)bn * 128 * p.ldb;
    else         Bp += bn * 128;

    float acc[4][4][4];
    #pragma unroll
    for (int i = 0; i < 4; i++)
        #pragma unroll
        for (int j = 0; j < 4; j++)
            #pragma unroll
            for (int r = 0; r < 4; r++) acc[i][j][r] = 0.f;

    for (int k0 = 0; k0 < p.K; k0 += 32) {
        // ---- Load A tile: 128 rows x 32 k, permute to fragment order ----
        #pragma unroll
        for (int t = 0; t < 4; t++) {
            const int idx = tid + 256 * t;
            const int row = idx >> 3;        // 0..127 (m)
            const int col4 = idx & 7;        // k-group of 4
            float4 v = *(const float4*)(A + (size_t)row * p.lda + k0 + col4 * 4);
            const int kstep = col4 >> 1;     // k8 block
            const int chi   = col4 & 1;      // k within 8: 0..3 or 4..7
            const int mtile = row >> 4;
            const int m8    = row & 7;
            const int reg   = ((row >> 3) & 1) + 2 * chi;
            uint32_t* dst = &As[(((kstep * 8 + mtile) * 32) + (m8 << 2)) * 4 + reg];
            dst[0]  = f2tf32(v.x);
            dst[4]  = f2tf32(v.y);
            dst[8]  = f2tf32(v.z);
            dst[12] = f2tf32(v.w);
        }

        // ---- Load B tile ----
        if (TRANS_B) {
            // B is [N,K] K-major: rows are n (128), cols k (32)
            #pragma unroll
            for (int t = 0; t < 4; t++) {
                const int idx = tid + 256 * t;
                const int row = idx >> 3;    // n local
                const int col4 = idx & 7;
                float4 v = *(const float4*)(Bp + (size_t)row * p.ldb + k0 + col4 * 4);
                const int kstep = col4 >> 1;
                const int chi   = col4 & 1;  // reg
                const int ntile = row >> 3;
                const int n8    = row & 7;
                uint32_t* dst = &Bs[(((kstep * 16 + ntile) * 32) + (n8 << 2)) * 2 + chi];
                dst[0] = f2tf32(v.x);
                dst[2] = f2tf32(v.y);
                dst[4] = f2tf32(v.z);
                dst[6] = f2tf32(v.w);
            }
        } else {
            // B is [K,N] N-major: rows k (32), cols n (128)
            #pragma unroll
            for (int t = 0; t < 4; t++) {
                const int idx = tid + 256 * t;
                const int rowk = idx >> 5;   // k local 0..31
                const int col4 = idx & 31;   // n group of 4
                const int n_l = col4 * 4;
                float4 v = *(const float4*)(Bp + (size_t)(k0 + rowk) * p.ldb + n_l);
                const int kstep = rowk >> 3;
                const int k8    = rowk & 7;
                const int ck    = k8 & 3;
                const int chi   = k8 >> 2;   // reg
                const int ntile = n_l >> 3;
                uint32_t* dst = &Bs[(((kstep * 16 + ntile) * 32) + ((n_l & 7) << 2) + ck) * 2 + chi];
                dst[0]  = f2tf32(v.x);
                dst[8]  = f2tf32(v.y);
                dst[16] = f2tf32(v.z);
                dst[24] = f2tf32(v.w);
            }
        }
        __syncthreads();

        // ---- Compute: 4 k-steps of 8 ----
        #pragma unroll
        for (int ks = 0; ks < 4; ks++) {
            uint32_t af[4][4];
            uint32_t bf[4][2];
            #pragma unroll
            for (int mt = 0; mt < 4; mt++) {
                uint4 v = *(const uint4*)&As[(((ks * 8 + warp_m * 4 + mt) * 32) + lane) * 4];
                af[mt][0] = v.x; af[mt][1] = v.y; af[mt][2] = v.z; af[mt][3] = v.w;
            }
            #pragma unroll
            for (int nt = 0; nt < 4; nt++) {
                uint2 v = *(const uint2*)&Bs[(((ks * 16 + warp_n * 4 + nt) * 32) + lane) * 2];
                bf[nt][0] = v.x; bf[nt][1] = v.y;
            }
            #pragma unroll
            for (int mt = 0; mt < 4; mt++)
                #pragma unroll
                for (int nt = 0; nt < 4; nt++)
                    mma_tf32(acc[mt][nt], af[mt], bf[nt]);
        }
        __syncthreads();
    }

    // ---- Epilogue ----
    const size_t coff = (size_t)(z / p.divH) * p.strideCb +
                        (size_t)(z % p.divH) * p.strideCh;
    const int r  = lane >> 2;
    const int c2 = (lane & 3) * 2;

    #pragma unroll
    for (int mt = 0; mt < 4; mt++) {
        #pragma unroll
        for (int nt = 0; nt < 4; nt++) {
            const int n = bn * 128 + warp_n * 32 + nt * 8 + c2;
            float b0 = 0.f, b1 = 0.f;
            if (p.bias) {
                float2 bb = *(const float2*)&p.bias[n];
                b0 = bb.x; b1 = bb.y;
            }
            #pragma unroll
            for (int half = 0; half < 2; half++) {
                const int m = bm * 128 + warp_m * 64 + mt * 16 + r + half * 8;
                const float v0 = acc[mt][nt][half * 2 + 0] * p.alpha + b0;
                const float v1 = acc[mt][nt][half * 2 + 1] * p.alpha + b1;
                if (EPI == 1) {
                    const int b = m >> 10;
                    const int s = m & 1023;
                    const int h = n / F3;
                    const int f = n - h * F3;
                    *(float2*)&g_qkv[(((size_t)(b * Hn + h)) * Sn + s) * F3 + f] =
                        make_float2(v0, v1);
                } else {
                    *(float2*)&p.C[coff + (size_t)m * p.ldc + n] = make_float2(v0, v1);
                }
            }
        }
    }
}

// Softmax over rows of g_scores: one block (256 thr) per 1024-element row.
__global__ void __launch_bounds__(256) softmax_kernel(float* sc)
{
    float* row = sc + (size_t)blockIdx.x * Sn;
    const int tid = threadIdx.x;
    const int lane = tid & 31;
    const int wid = tid >> 5;
    __shared__ float red[8];

    float4 v = ((const float4*)row)[tid];
    float m = fmaxf(fmaxf(v.x, v.y), fmaxf(v.z, v.w));
    #pragma unroll
    for (int o = 16; o; o >>= 1) m = fmaxf(m, __shfl_xor_sync(~0u, m, o));
    if (lane == 0) red[wid] = m;
    __syncthreads();
    float bm = red[0];
    #pragma unroll
    for (int i = 1; i < 8; i++) bm = fmaxf(bm, red[i]);
    __syncthreads();

    float4 e;
    e.x = __expf(v.x - bm);
    e.y = __expf(v.y - bm);
    e.z = __expf(v.z - bm);
    e.w = __expf(v.w - bm);
    float s = e.x + e.y + e.z + e.w;
    #pragma unroll
    for (int o = 16; o; o >>= 1) s += __shfl_xor_sync(~0u, s, o);
    if (lane == 0) red[wid] = s;
    __syncthreads();
    float bs = red[0];
    #pragma unroll
    for (int i = 1; i < 8; i++) bs += red[i];
    const float rdiv = __frcp_rn(bs);

    e.x *= rdiv; e.y *= rdiv; e.z *= rdiv; e.w *= rdiv;
    ((float4*)row)[tid] = e;
}

extern "C" void kernel_launch(void* const* d_in, const int* in_sizes, int n_in,
                              void* d_out, int out_size)
{
    const float* x     = (const float*)d_in[0];  // [B,S,E]
    const float* qkv_w = (const float*)d_in[1];  // [H,3E,E]
    const float* qkv_b = (const float*)d_in[2];  // [H,3E]
    const float* out_w = (const float*)d_in[3];  // [E,H*E]
    const float* out_b = (const float*)d_in[4];  // [E]
    float* out = (float*)d_out;                  // [B,S,E]

    float *qkv, *scores, *concat;
    cudaGetSymbolAddress((void**)&qkv,    g_qkv);
    cudaGetSymbolAddress((void**)&scores, g_scores);
    cudaGetSymbolAddress((void**)&concat, g_concat);

    // 1) QKV projection: [8192,768] x [27648,768]^T -> scatter [B,H,S,3E], +bias
    {
        GemmParams p = {};
        p.A = x; p.B = qkv_w; p.C = qkv;
        p.K = En; p.lda = En; p.ldb = En; p.ldc = 0;
        p.strideAz = 0; p.strideBz = 0;
        p.strideCb = 0; p.strideCh = 0; p.divH = 1;
        p.bias = qkv_b; p.alpha = 1.0f;
        gemm_tc<true, 1><<<dim3(NQKV / 128, (Bn * Sn) / 128, 1), 256>>>(p);
    }

    // 2) Scores: per (b,h): Q[1024,768] x K[1024,768]^T * scale
    {
        GemmParams p = {};
        p.A = qkv; p.B = qkv + En; p.C = scores;
        p.K = En; p.lda = F3; p.ldb = F3; p.ldc = Sn;
        p.strideAz = (long long)Sn * F3;
        p.strideBz = (long long)Sn * F3;
        p.strideCb = (long long)Sn * Sn; p.strideCh = 0; p.divH = 1;
        p.bias = nullptr; p.alpha = 0.036084391824351615f; // 1/sqrt(768)
        gemm_tc<true, 0><<<dim3(Sn / 128, Sn / 128, Bn * Hn), 256>>>(p);
    }

    // 3) Softmax rows
    softmax_kernel<<<Bn * Hn * Sn, 256>>>(scores);

    // 4) AV: per (b,h): P[1024,1024] x V[1024,768] -> concat [B,S,H,E]
    {
        GemmParams p = {};
        p.A = scores; p.B = qkv + 2 * En; p.C = concat;
        p.K = Sn; p.lda = Sn; p.ldb = F3; p.ldc = HE;
        p.strideAz = (long long)Sn * Sn;
        p.strideBz = (long long)Sn * F3;
        p.strideCb = (long long)Sn * Hn * En;
        p.strideCh = En;
        p.divH = Hn;
        p.bias = nullptr; p.alpha = 1.0f;
        gemm_tc<false, 0><<<dim3(En / 128, Sn / 128, Bn * Hn), 256>>>(p);
    }

    // 5) Output projection: [8192,9216] x [768,9216]^T + bias -> [8192,768]
    {
        GemmParams p = {};
        p.A = concat; p.B = out_w; p.C = out;
        p.K = HE; p.lda = HE; p.ldb = HE; p.ldc = En;
        p.strideAz = 0; p.strideBz = 0;
        p.strideCb = 0; p.strideCh = 0; p.divH = 1;
        p.bias = out_b; p.alpha = 1.0f;
        gemm_tc<true, 0><<<dim3(En / 128, (Bn * Sn) / 128, 1), 256>>>(p);
    }
}

// round 3
// speedup vs baseline: 3.1774x; 1.3900x over previous
#include <cuda_runtime.h>
#include <math.h>
#include <stdint.h>

// Problem constants
#define Bn 8
#define Sn 1024
#define En 768
#define Hn 12
#define F3 (3 * En)          // 2304
#define NQKV (Hn * F3)       // 27648
#define HE (Hn * En)         // 9216

// Scratch (allocation-free: __device__ globals)
__device__ float g_qkv[(size_t)Bn * Hn * Sn * F3];     // [B,H,S,3E]
__device__ float g_scores[(size_t)Bn * Hn * Sn * Sn];  // [B*H,S,S]
__device__ float g_vT[(size_t)Bn * Hn * En * Sn];      // [B*H,E,S]
__device__ float g_concat[(size_t)Bn * Sn * Hn * En];  // [B,S,H,E]

struct GemmParams {
    const float* A;   // [M,K] K-major, row stride lda
    const float* B;   // [N,K] K-major, row stride ldb
    float* C;
    int K;
    int lda, ldb, ldc;
    long long strideAz, strideBz;
    long long strideCb, strideCh;
    int divH;
    const float* bias;
    float alpha;
};

__device__ __forceinline__ uint32_t f2tf32(float x) {
    uint32_t r;
    asm("cvt.rna.tf32.f32 %0, %1;" : "=r"(r) : "f"(x));
    return r;
}

__device__ __forceinline__ void mma_tf32(float* d, const uint32_t* a, const uint32_t* b) {
    asm volatile(
        "mma.sync.aligned.m16n8k8.row.col.f32.tf32.tf32.f32 "
        "{%0,%1,%2,%3}, {%4,%5,%6,%7}, {%8,%9}, {%0,%1,%2,%3};"
        : "+f"(d[0]), "+f"(d[1]), "+f"(d[2]), "+f"(d[3])
        : "r"(a[0]), "r"(a[1]), "r"(a[2]), "r"(a[3]), "r"(b[0]), "r"(b[1]));
}

// Tensor-core tf32 GEMM, A[M,K] x B[N,K]^T. Tile 128x128x32.
// 8 warps (2 M x 4 N), warp tile 64x32.
// SMEM layout: fragment-order with XOR(kstep) swizzle -> all LDS/STS conflict-free.
//   A word: frag*128 + (lane>>3)*32 + (((lane&7)^kstep)<<2) + reg, frag = kstep*8+mtile
//   B word: frag*64  + (lane>>4)*32 + (((lane&15)^kstep)<<1) + reg, frag = kstep*16+ntile
// EPI: 0 = plain C write, 1 = QKV scatter to [B,H,S,3E]
template <int EPI>
__global__ void __launch_bounds__(256, 2) gemm_tc(GemmParams p)
{
    __shared__ uint32_t As[4 * 8 * 32 * 4];   // 16 KB
    __shared__ uint32_t Bs[4 * 16 * 32 * 2];  // 16 KB

    const int tid = threadIdx.x;
    const int lane = tid & 31;
    const int wid = tid >> 5;
    const int warp_m = wid & 1;   // 0..1
    const int warp_n = wid >> 1;  // 0..3

    const int bn = blockIdx.x;
    const int bm = blockIdx.y;
    const int z  = blockIdx.z;

    const float* A = p.A + (size_t)z * p.strideAz + (size_t)bm * 128 * p.lda;
    const float* Bp = p.B + (size_t)z * p.strideBz + (size_t)bn * 128 * p.ldb;

    // A thread mapping: 5-bit permutation of row group so each warp spans
    // rowbit3 (g0) and rowbit0 (g1) -> store banks cover all 32.
    const int gA = tid >> 3;
    const int col4 = tid & 7;
    const int rowpA = ((gA & 1) << 3) | ((gA >> 1) & 1) | (((gA >> 2) & 1) << 1)
                    | (((gA >> 3) & 1) << 2) | (gA & 16);
    const int kstepL = col4 >> 1;   // k8 step of this thread's float4
    const int chi    = col4 & 1;    // k-half within 8

    float acc[4][4][4];
    #pragma unroll
    for (int i = 0; i < 4; i++)
        #pragma unroll
        for (int j = 0; j < 4; j++)
            #pragma unroll
            for (int r = 0; r < 4; r++) acc[i][j][r] = 0.f;

    for (int k0 = 0; k0 < p.K; k0 += 32) {
        // ---- Store A tile in fragment order (conflict-free) ----
        #pragma unroll
        for (int t = 0; t < 4; t++) {
            const int row = rowpA + 32 * t;
            float4 v = *(const float4*)(A + (size_t)row * p.lda + k0 + col4 * 4);
            const int mtile = row >> 4;
            const int m8 = row & 7;
            const int reg = ((row >> 3) & 1) + 2 * chi;
            const int frag = kstepL * 8 + mtile;
            const uint32_t base = frag * 128 + (m8 >> 1) * 32 + reg;
            float c[4] = {v.x, v.y, v.z, v.w};
            #pragma unroll
            for (int jj = 0; jj < 4; jj++) {
                const int lan = m8 * 4 + jj;
                As[base + (((lan & 7) ^ kstepL) << 2)] = f2tf32(c[jj]);
            }
        }

        // ---- Store B tile in fragment order (conflict-free) ----
        #pragma unroll
        for (int t = 0; t < 4; t++) {
            const int idx = tid + 256 * t;
            const int row = idx >> 3;            // n local
            float4 v = *(const float4*)(Bp + (size_t)row * p.ldb + k0 + col4 * 4);
            const int ntile = row >> 3;
            const int n8 = row & 7;
            const int frag = kstepL * 16 + ntile;
            const uint32_t base = frag * 64 + ((n8 * 4) >> 4) * 32 + chi;
            float c[4] = {v.x, v.y, v.z, v.w};
            #pragma unroll
            for (int jj = 0; jj < 4; jj++) {
                const int lan = n8 * 4 + jj;
                Bs[base + ((((lan & 15) ^ kstepL)) << 1)] = f2tf32(c[jj]);
            }
        }
        __syncthreads();

        // ---- Compute: 4 k-steps of 8 ----
        #pragma unroll
        for (int ks = 0; ks < 4; ks++) {
            uint32_t af[4][4];
            uint32_t bf[4][2];
            #pragma unroll
            for (int mt = 0; mt < 4; mt++) {
                const int frag = ks * 8 + warp_m * 4 + mt;
                uint4 v = *(const uint4*)&As[frag * 128 + (lane >> 3) * 32 +
                                             (((lane & 7) ^ ks) << 2)];
                af[mt][0] = v.x; af[mt][1] = v.y; af[mt][2] = v.z; af[mt][3] = v.w;
            }
            #pragma unroll
            for (int nt = 0; nt < 4; nt++) {
                const int frag = ks * 16 + warp_n * 4 + nt;
                uint2 v = *(const uint2*)&Bs[frag * 64 + (lane >> 4) * 32 +
                                             (((lane & 15) ^ ks) << 1)];
                bf[nt][0] = v.x; bf[nt][1] = v.y;
            }
            #pragma unroll
            for (int mt = 0; mt < 4; mt++)
                #pragma unroll
                for (int nt = 0; nt < 4; nt++)
                    mma_tf32(acc[mt][nt], af[mt], bf[nt]);
        }
        __syncthreads();
    }

    // ---- Epilogue ----
    const size_t coff = (size_t)(z / p.divH) * p.strideCb +
                        (size_t)(z % p.divH) * p.strideCh;
    const int r  = lane >> 2;
    const int c2 = (lane & 3) * 2;

    #pragma unroll
    for (int mt = 0; mt < 4; mt++) {
        #pragma unroll
        for (int nt = 0; nt < 4; nt++) {
            const int n = bn * 128 + warp_n * 32 + nt * 8 + c2;
            float b0 = 0.f, b1 = 0.f;
            if (p.bias) {
                float2 bb = *(const float2*)&p.bias[n];
                b0 = bb.x; b1 = bb.y;
            }
            #pragma unroll
            for (int half = 0; half < 2; half++) {
                const int m = bm * 128 + warp_m * 64 + mt * 16 + r + half * 8;
                const float v0 = acc[mt][nt][half * 2 + 0] * p.alpha + b0;
                const float v1 = acc[mt][nt][half * 2 + 1] * p.alpha + b1;
                if (EPI == 1) {
                    const int b = m >> 10;
                    const int s = m & 1023;
                    const int h = n / F3;
                    const int f = n - h * F3;
                    *(float2*)&g_qkv[(((size_t)(b * Hn + h)) * Sn + s) * F3 + f] =
                        make_float2(v0, v1);
                } else {
                    *(float2*)&p.C[coff + (size_t)m * p.ldc + n] = make_float2(v0, v1);
                }
            }
        }
    }
}

// Transpose V slab of qkv: vT[bh, e, s] = qkv[bh, s, 2E + e]
__global__ void __launch_bounds__(256) transpose_v()
{
    __shared__ float tile[32][33];
    const int bh = blockIdx.z;
    const int s0 = blockIdx.x * 32;
    const int e0 = blockIdx.y * 32;
    const int tx = threadIdx.x;   // 0..31
    const int ty = threadIdx.y;   // 0..7
    const float* src = g_qkv + ((size_t)bh * Sn) * F3 + 2 * En;
    float* dst = g_vT + ((size_t)bh * En) * Sn;

    #pragma unroll
    for (int j = 0; j < 4; j++)
        tile[ty + 8 * j][tx] = src[(size_t)(s0 + ty + 8 * j) * F3 + e0 + tx];
    __syncthreads();
    #pragma unroll
    for (int j = 0; j < 4; j++)
        dst[(size_t)(e0 + ty + 8 * j) * Sn + s0 + tx] = tile[tx][ty + 8 * j];
}

// Softmax over rows of g_scores: one block (256 thr) per 1024-element row.
__global__ void __launch_bounds__(256) softmax_kernel(float* sc)
{
    float* row = sc + (size_t)blockIdx.x * Sn;
    const int tid = threadIdx.x;
    const int lane = tid & 31;
    const int wid = tid >> 5;
    __shared__ float red[8];

    float4 v = ((const float4*)row)[tid];
    float m = fmaxf(fmaxf(v.x, v.y), fmaxf(v.z, v.w));
    #pragma unroll
    for (int o = 16; o; o >>= 1) m = fmaxf(m, __shfl_xor_sync(~0u, m, o));
    if (lane == 0) red[wid] = m;
    __syncthreads();
    float bm = red[0];
    #pragma unroll
    for (int i = 1; i < 8; i++) bm = fmaxf(bm, red[i]);
    __syncthreads();

    float4 e;
    e.x = __expf(v.x - bm);
    e.y = __expf(v.y - bm);
    e.z = __expf(v.z - bm);
    e.w = __expf(v.w - bm);
    float s = e.x + e.y + e.z + e.w;
    #pragma unroll
    for (int o = 16; o; o >>= 1) s += __shfl_xor_sync(~0u, s, o);
    if (lane == 0) red[wid] = s;
    __syncthreads();
    float bs = red[0];
    #pragma unroll
    for (int i = 1; i < 8; i++) bs += red[i];
    const float rdiv = __frcp_rn(bs);

    e.x *= rdiv; e.y *= rdiv; e.z *= rdiv; e.w *= rdiv;
    ((float4*)row)[tid] = e;
}

extern "C" void kernel_launch(void* const* d_in, const int* in_sizes, int n_in,
                              void* d_out, int out_size)
{
    const float* x     = (const float*)d_in[0];  // [B,S,E]
    const float* qkv_w = (const float*)d_in[1];  // [H,3E,E]
    const float* qkv_b = (const float*)d_in[2];  // [H,3E]
    const float* out_w = (const float*)d_in[3];  // [E,H*E]
    const float* out_b = (const float*)d_in[4];  // [E]
    float* out = (float*)d_out;                  // [B,S,E]

    float *qkv, *scores, *vT, *concat;
    cudaGetSymbolAddress((void**)&qkv,    g_qkv);
    cudaGetSymbolAddress((void**)&scores, g_scores);
    cudaGetSymbolAddress((void**)&vT,     g_vT);
    cudaGetSymbolAddress((void**)&concat, g_concat);

    // 1) QKV projection: [8192,768] x [27648,768]^T -> scatter [B,H,S,3E], +bias
    {
        GemmParams p = {};
        p.A = x; p.B = qkv_w; p.C = qkv;
        p.K = En; p.lda = En; p.ldb = En; p.ldc = 0;
        p.strideAz = 0; p.strideBz = 0;
        p.strideCb = 0; p.strideCh = 0; p.divH = 1;
        p.bias = qkv_b; p.alpha = 1.0f;
        gemm_tc<1><<<dim3(NQKV / 128, (Bn * Sn) / 128, 1), 256>>>(p);
    }

    // 1b) Transpose V slab -> vT [B*H, E, S]
    transpose_v<<<dim3(Sn / 32, En / 32, Bn * Hn), dim3(32, 8)>>>();

    // 2) Scores: per (b,h): Q[1024,768] x K[1024,768]^T * scale
    {
        GemmParams p = {};
        p.A = qkv; p.B = qkv + En; p.C = scores;
        p.K = En; p.lda = F3; p.ldb = F3; p.ldc = Sn;
        p.strideAz = (long long)Sn * F3;
        p.strideBz = (long long)Sn * F3;
        p.strideCb = (long long)Sn * Sn; p.strideCh = 0; p.divH = 1;
        p.bias = nullptr; p.alpha = 0.036084391824351615f; // 1/sqrt(768)
        gemm_tc<0><<<dim3(Sn / 128, Sn / 128, Bn * Hn), 256>>>(p);
    }

    // 3) Softmax rows
    softmax_kernel<<<Bn * Hn * Sn, 256>>>(scores);

    // 4) AV: per (b,h): P[1024,1024] x vT[768,1024]^T -> concat [B,S,H,E]
    {
        GemmParams p = {};
        p.A = scores; p.B = vT; p.C = concat;
        p.K = Sn; p.lda = Sn; p.ldb = Sn; p.ldc = HE;
        p.strideAz = (long long)Sn * Sn;
        p.strideBz = (long long)En * Sn;
        p.strideCb = (long long)Sn * Hn * En;
        p.strideCh = En;
        p.divH = Hn;
        p.bias = nullptr; p.alpha = 1.0f;
        gemm_tc<0><<<dim3(En / 128, Sn / 128, Bn * Hn), 256>>>(p);
    }

    // 5) Output projection: [8192,9216] x [768,9216]^T + bias -> [8192,768]
    {
        GemmParams p = {};
        p.A = concat; p.B = out_w; p.C = out;
        p.K = HE; p.lda = HE; p.ldb = HE; p.ldc = En;
        p.strideAz = 0; p.strideBz = 0;
        p.strideCb = 0; p.strideCh = 0; p.divH = 1;
        p.bias = out_b; p.alpha = 1.0f;
        gemm_tc<0><<<dim3(En / 128, (Bn * Sn) / 128, 1), 256>>>(p);
    }
}